// round 1
// baseline (speedup 1.0000x reference)
#include <cuda_runtime.h>
#include <math.h>

#define NBLK 32
#define CAP 1024
#define DK 256
#define DH 768
#define NQ 8192
#define CK 32

// scratch (device globals: no allocation allowed)
__device__ float g_q[NQ * DK];   // layernormed queries, 8 MB
__device__ float g_r[NQ * DK];   // retrieved values, 8 MB

// ---------------------------------------------------------------------------
// Kernel A: q = LayerNorm(hs @ Wk + bk) * ln_w + ln_b      [8192,768]x[768,256]
// BM=64, BN=256 (full row in CTA so LN is a warp reduce), BK=16, 256 threads,
// each thread an 8x8 register tile. Warp == 8 rows, lanes span the 256 cols.
// ---------------------------------------------------------------------------
__global__ __launch_bounds__(256) void qproj_ln_kernel(
    const float* __restrict__ hs, const float* __restrict__ Wk,
    const float* __restrict__ bk, const float* __restrict__ lnw,
    const float* __restrict__ lnb)
{
    __shared__ float As[64][16];
    __shared__ float Bs[16][256];
    const int tid = threadIdx.x;
    const int ty = tid >> 5;      // warp id 0..7  -> rows ty*8..ty*8+7
    const int tx = tid & 31;      // lane -> cols tx*8..tx*8+7
    const int m0 = blockIdx.x * 64;

    float c[8][8];
#pragma unroll
    for (int i = 0; i < 8; i++)
#pragma unroll
        for (int j = 0; j < 8; j++) c[i][j] = 0.f;

    for (int k0 = 0; k0 < DH; k0 += 16) {
        // As: 64x16 = 256 float4, one per thread
        {
            int r = tid >> 2, k4 = tid & 3;
            float4 v = *(const float4*)(hs + (size_t)(m0 + r) * DH + k0 + k4 * 4);
            *(float4*)(&As[r][k4 * 4]) = v;
        }
        // Bs: 16x256 = 1024 float4, 4 per thread
#pragma unroll
        for (int u = 0; u < 4; u++) {
            int idx4 = tid + u * 256;
            int kk = idx4 >> 6, c4 = idx4 & 63;
            float4 v = *(const float4*)(Wk + (size_t)(k0 + kk) * DK + c4 * 4);
            *(float4*)(&Bs[kk][c4 * 4]) = v;
        }
        __syncthreads();
#pragma unroll
        for (int kk = 0; kk < 16; kk++) {
            float a[8], b[8];
#pragma unroll
            for (int i = 0; i < 8; i++) a[i] = As[ty * 8 + i][kk];   // broadcast
            float4 b0 = *(float4*)(&Bs[kk][tx * 8]);
            float4 b1 = *(float4*)(&Bs[kk][tx * 8 + 4]);
            b[0] = b0.x; b[1] = b0.y; b[2] = b0.z; b[3] = b0.w;
            b[4] = b1.x; b[5] = b1.y; b[6] = b1.z; b[7] = b1.w;
#pragma unroll
            for (int i = 0; i < 8; i++)
#pragma unroll
                for (int j = 0; j < 8; j++) c[i][j] += a[i] * b[j];
        }
        __syncthreads();
    }

    float bkv[8], lw[8], lb[8];
#pragma unroll
    for (int j = 0; j < 8; j++) {
        int col = tx * 8 + j;
        bkv[j] = bk[col]; lw[j] = lnw[col]; lb[j] = lnb[col];
    }
#pragma unroll
    for (int i = 0; i < 8; i++)
#pragma unroll
        for (int j = 0; j < 8; j++) c[i][j] += bkv[j];

    // LayerNorm per row: each row's 256 cols live in one warp (8 per lane)
#pragma unroll
    for (int i = 0; i < 8; i++) {
        float s = 0.f;
#pragma unroll
        for (int j = 0; j < 8; j++) s += c[i][j];
#pragma unroll
        for (int o = 16; o > 0; o >>= 1) s += __shfl_xor_sync(0xffffffffu, s, o);
        float mu = s * (1.0f / 256.0f);
        float v = 0.f;
#pragma unroll
        for (int j = 0; j < 8; j++) { float d = c[i][j] - mu; v += d * d; }
#pragma unroll
        for (int o = 16; o > 0; o >>= 1) v += __shfl_xor_sync(0xffffffffu, v, o);
        float rs = rsqrtf(v * (1.0f / 256.0f) + 1e-5f);
        float out[8];
#pragma unroll
        for (int j = 0; j < 8; j++) out[j] = (c[i][j] - mu) * rs * lw[j] + lb[j];
        float* dst = g_q + (size_t)(m0 + ty * 8 + i) * DK + tx * 8;
        *(float4*)dst       = make_float4(out[0], out[1], out[2], out[3]);
        *(float4*)(dst + 4) = make_float4(out[4], out[5], out[6], out[7]);
    }
}

// ---------------------------------------------------------------------------
// Kernel B: per-block masked softmax attention, summed over blocks.
// CTA = 64 queries x all 32 memory blocks, streamed in 32-key chunks.
// 512 threads: warp ty (0..15) owns query rows ty*4..ty*4+3; lane tx = key id
// within chunk for QK^T, and cols tx*8..tx*8+7 for P@V.
// Chunks beyond block_usage[b] are skipped entirely (expected ~48% of work).
// exp without max-subtraction is exact vs reference (scores are per-block
// softmaxed; subtraction cancels) and safe (|s| << 1).
// ---------------------------------------------------------------------------
extern __shared__ float smem_attn[];

__global__ __launch_bounds__(512, 1) void attn_kernel(
    const float* __restrict__ mk, const float* __restrict__ mv,
    const int* __restrict__ usage)
{
    float* Qs  = smem_attn;            // [64][256]           65536 B
    float* Vs  = Qs + 64 * 256;        // [32][256]           32768 B
    float* Ps  = Vs + 32 * 256;        // [32][65] padded      8320 B
    float* Kts = Ps + 32 * 65;         // [256][33] d-major   33792 B

    const int tid = threadIdx.x;
    const int ty = tid >> 5;          // warp 0..15
    const int tx = tid & 31;          // lane
    const int q0 = blockIdx.x * 64;

    // load Q tile (reused against all 32768 keys)
#pragma unroll
    for (int u = 0; u < 8; u++) {
        int idx4 = tid + u * 512;
        int r = idx4 >> 6, c4 = idx4 & 63;
        float4 v = *(const float4*)(g_q + (size_t)(q0 + r) * DK + c4 * 4);
        *(float4*)(Qs + r * 256 + c4 * 4) = v;
    }

    float O[4][8];
#pragma unroll
    for (int i = 0; i < 4; i++)
#pragma unroll
        for (int j = 0; j < 8; j++) O[i][j] = 0.f;

    for (int b = 0; b < NBLK; b++) {
        const int use = __ldg(usage + b);
        const int nch = (use + CK - 1) / CK;

        float acc[4][8];
#pragma unroll
        for (int i = 0; i < 4; i++)
#pragma unroll
            for (int j = 0; j < 8; j++) acc[i][j] = 0.f;
        float l[4] = {0.f, 0.f, 0.f, 0.f};

        for (int ch = 0; ch < nch; ch++) {
            const int c0 = ch * CK;
            __syncthreads();   // previous chunk's Ps/Vs consumed
            // load K chunk transposed (d-major) + V chunk
            const float* kb = mk + ((size_t)b * CAP + c0) * DK;
            const float* vb = mv + ((size_t)b * CAP + c0) * DK;
#pragma unroll
            for (int u = 0; u < 4; u++) {
                int idx4 = tid + u * 512;
                int key = idx4 >> 6, d4 = idx4 & 63;
                float4 kv = *(const float4*)(kb + (size_t)key * DK + d4 * 4);
                Kts[(d4 * 4 + 0) * 33 + key] = kv.x;
                Kts[(d4 * 4 + 1) * 33 + key] = kv.y;
                Kts[(d4 * 4 + 2) * 33 + key] = kv.z;
                Kts[(d4 * 4 + 3) * 33 + key] = kv.w;
                float4 vv = *(const float4*)(vb + (size_t)key * DK + d4 * 4);
                *(float4*)(Vs + key * 256 + d4 * 4) = vv;
            }
            __syncthreads();

            // S = Q K^T : lane tx owns key tx; rows ty*4..+3
            float s[4] = {0.f, 0.f, 0.f, 0.f};
#pragma unroll 8
            for (int d4 = 0; d4 < 64; d4++) {
                float k0v = Kts[(d4 * 4 + 0) * 33 + tx];
                float k1v = Kts[(d4 * 4 + 1) * 33 + tx];
                float k2v = Kts[(d4 * 4 + 2) * 33 + tx];
                float k3v = Kts[(d4 * 4 + 3) * 33 + tx];
#pragma unroll
                for (int i = 0; i < 4; i++) {
                    float4 qv = *(float4*)(Qs + (ty * 4 + i) * 256 + d4 * 4);
                    s[i] += qv.x * k0v + qv.y * k1v + qv.z * k2v + qv.w * k3v;
                }
            }
            const bool valid = (c0 + tx) < use;
#pragma unroll
            for (int i = 0; i < 4; i++) {
                float p = valid ? __expf(s[i] * 0.0625f) : 0.f;
                l[i] += p;
                Ps[tx * 65 + ty * 4 + i] = p;   // padded: conflict-free
            }
            __syncthreads();

            // acc += P @ V : thread owns rows ty*4..+3, cols tx*8..+7
#pragma unroll 4
            for (int c = 0; c < CK; c++) {
                float4 v0 = *(float4*)(Vs + c * 256 + tx * 8);
                float4 v1 = *(float4*)(Vs + c * 256 + tx * 8 + 4);
#pragma unroll
                for (int i = 0; i < 4; i++) {
                    float pp = Ps[c * 65 + ty * 4 + i];   // broadcast
                    acc[i][0] += pp * v0.x; acc[i][1] += pp * v0.y;
                    acc[i][2] += pp * v0.z; acc[i][3] += pp * v0.w;
                    acc[i][4] += pp * v1.x; acc[i][5] += pp * v1.y;
                    acc[i][6] += pp * v1.z; acc[i][7] += pp * v1.w;
                }
            }
        }
        // finalize block: O += acc / sum_exp   (lanes hold partial l per key)
#pragma unroll
        for (int i = 0; i < 4; i++) {
            float ls = l[i];
#pragma unroll
            for (int o = 16; o > 0; o >>= 1) ls += __shfl_xor_sync(0xffffffffu, ls, o);
            float rl = 1.0f / ls;
#pragma unroll
            for (int j = 0; j < 8; j++) O[i][j] += acc[i][j] * rl;
        }
    }

#pragma unroll
    for (int i = 0; i < 4; i++) {
        float* dst = g_r + (size_t)(q0 + ty * 4 + i) * DK + tx * 8;
        *(float4*)dst       = make_float4(O[i][0], O[i][1], O[i][2], O[i][3]);
        *(float4*)(dst + 4) = make_float4(O[i][4], O[i][5], O[i][6], O[i][7]);
    }
}

// ---------------------------------------------------------------------------
// Kernel C: out = retrieved @ Wo + bo          [8192,256]x[256,768]
// BM=64, BN=64, BK=16, 256 threads, 4x4 register tiles.
// ---------------------------------------------------------------------------
__global__ __launch_bounds__(256) void out_gemm_kernel(
    const float* __restrict__ Wo, const float* __restrict__ bo,
    float* __restrict__ out)
{
    __shared__ float As[64][20];   // pad 20: float4-store aligned, no bank hits
    __shared__ float Bs[16][64];
    const int tid = threadIdx.x;
    const int ty = tid >> 4;      // 0..15 -> rows ty*4..+3
    const int tx = tid & 15;      // cols tx*4..+3
    const int m0 = blockIdx.x * 64;
    const int n0 = blockIdx.y * 64;

    float c[4][4];
#pragma unroll
    for (int i = 0; i < 4; i++)
#pragma unroll
        for (int j = 0; j < 4; j++) c[i][j] = 0.f;

    for (int k0 = 0; k0 < DK; k0 += 16) {
        {
            int r = tid >> 2, k4 = tid & 3;
            float4 v = *(const float4*)(g_r + (size_t)(m0 + r) * DK + k0 + k4 * 4);
            *(float4*)(&As[r][k4 * 4]) = v;
        }
        {
            int kk = tid >> 4, c4 = tid & 15;
            float4 v = *(const float4*)(Wo + (size_t)(k0 + kk) * DH + n0 + c4 * 4);
            *(float4*)(&Bs[kk][c4 * 4]) = v;
        }
        __syncthreads();
#pragma unroll
        for (int kk = 0; kk < 16; kk++) {
            float a[4];
#pragma unroll
            for (int i = 0; i < 4; i++) a[i] = As[ty * 4 + i][kk];
            float4 bv = *(float4*)(&Bs[kk][tx * 4]);
            float b[4] = {bv.x, bv.y, bv.z, bv.w};
#pragma unroll
            for (int i = 0; i < 4; i++)
#pragma unroll
                for (int j = 0; j < 4; j++) c[i][j] += a[i] * b[j];
        }
        __syncthreads();
    }

    float4 bv = *(const float4*)(bo + n0 + tx * 4);
    float bb[4] = {bv.x, bv.y, bv.z, bv.w};
#pragma unroll
    for (int i = 0; i < 4; i++) {
        float4 r = make_float4(c[i][0] + bb[0], c[i][1] + bb[1],
                               c[i][2] + bb[2], c[i][3] + bb[3]);
        *(float4*)(out + (size_t)(m0 + ty * 4 + i) * DH + n0 + tx * 4) = r;
    }
}

// ---------------------------------------------------------------------------
extern "C" void kernel_launch(void* const* d_in, const int* in_sizes, int n_in,
                              void* d_out, int out_size)
{
    const float* hs  = (const float*)d_in[0];
    const float* Wk  = (const float*)d_in[1];
    const float* bk  = (const float*)d_in[2];
    const float* lnw = (const float*)d_in[3];
    const float* lnb = (const float*)d_in[4];
    const float* mk  = (const float*)d_in[5];
    const float* mv  = (const float*)d_in[6];
    const float* Wo  = (const float*)d_in[7];
    const float* bo  = (const float*)d_in[8];
    const int* usage = (const int*)d_in[9];
    float* out = (float*)d_out;

    const int attn_smem = (64 * 256 + 32 * 256 + 32 * 65 + 256 * 33) * (int)sizeof(float);
    // idempotent + deterministic every call; not a stream op, capture-safe
    cudaFuncSetAttribute(attn_kernel, cudaFuncAttributeMaxDynamicSharedMemorySize, attn_smem);

    qproj_ln_kernel<<<NQ / 64, 256>>>(hs, Wk, bk, lnw, lnb);
    attn_kernel<<<NQ / 64, 512, attn_smem>>>(mk, mv, usage);
    dim3 gc(NQ / 64, DH / 64);
    out_gemm_kernel<<<gc, 256>>>(Wo, bo, out);
}